// round 1
// baseline (speedup 1.0000x reference)
#include <cuda_runtime.h>
#include <math.h>

#define MM 4096
#define DD 2048
// inv_sqrt(4096) = 1/64 exactly
#define INV_SQRT_M 0.015625f

// ---------------- device scratch (no allocations allowed) ----------------
__device__ float g_qt[MM];
__device__ float g_k[MM];
__device__ float g_v[MM];
__device__ float g_it, g_ft, g_ot;
__device__ float g_kqt, g_denom;

// ---------------- kernel 1: matvecs + gates ----------------
// grid = 3*MM + 3 blocks, 256 threads.
//   b in [0,M):       qt[b]  = Wq[b]·x + bq[b]
//   b in [M,2M):      k[b-M] = (Wk·x + bk) / 64
//   b in [2M,3M):     v[..]  = Wv·x + bV
//   b == 3M:          it = exp(Wi·x + bi)
//   b == 3M+1:        ft = exp(Wf·x + bf)
//   b == 3M+2:        ot = sigmoid(Wo·x + bo)
__global__ __launch_bounds__(256) void mv_kernel(
    const float* __restrict__ x,
    const float* __restrict__ Wq, const float* __restrict__ bq,
    const float* __restrict__ Wk, const float* __restrict__ bk,
    const float* __restrict__ Wv, const float* __restrict__ bV,
    const float* __restrict__ Wi, const float* __restrict__ bi,
    const float* __restrict__ Wf, const float* __restrict__ bf,
    const float* __restrict__ Wo, const float* __restrict__ bo)
{
    const int b = blockIdx.x;
    const int t = threadIdx.x;

    const float* row;
    if (b < MM)            row = Wq + (size_t)b * DD;
    else if (b < 2 * MM)   row = Wk + (size_t)(b - MM) * DD;
    else if (b < 3 * MM)   row = Wv + (size_t)(b - 2 * MM) * DD;
    else if (b == 3 * MM)       row = Wi;
    else if (b == 3 * MM + 1)   row = Wf;
    else                        row = Wo;

    const float4* r4 = reinterpret_cast<const float4*>(row);
    const float4* x4 = reinterpret_cast<const float4*>(x);

    // 2048 floats = 512 float4; 256 threads -> 2 float4 each, coalesced
    float4 a0 = r4[t];
    float4 a1 = r4[t + 256];
    float4 c0 = x4[t];
    float4 c1 = x4[t + 256];
    float s = a0.x * c0.x + a0.y * c0.y + a0.z * c0.z + a0.w * c0.w
            + a1.x * c1.x + a1.y * c1.y + a1.z * c1.z + a1.w * c1.w;

    // warp reduce
    #pragma unroll
    for (int o = 16; o > 0; o >>= 1) s += __shfl_down_sync(0xFFFFFFFFu, s, o);

    __shared__ float ws[8];
    if ((t & 31) == 0) ws[t >> 5] = s;
    __syncthreads();
    if (t < 8) {
        float v = ws[t];
        #pragma unroll
        for (int o = 4; o > 0; o >>= 1) v += __shfl_down_sync(0xFFu, v, o);
        if (t == 0) {
            if (b < MM) {
                g_qt[b] = v + bq[b];
            } else if (b < 2 * MM) {
                g_k[b - MM] = INV_SQRT_M * (v + bk[b - MM]);
            } else if (b < 3 * MM) {
                g_v[b - 2 * MM] = v + bV[b - 2 * MM];
            } else if (b == 3 * MM) {
                g_it = expf(v + bi[0]);
            } else if (b == 3 * MM + 1) {
                g_ft = expf(v + bf[0]);
            } else {
                float z = v + bo[0];
                g_ot = 1.0f / (1.0f + expf(-z));
            }
        }
    }
}

// ---------------- kernel 2: n-update + tiny reductions ----------------
// 1 block, 1024 threads. Computes:
//   n_i = ft*n_prev_i + it*k_i  (written to output)
//   kqt = k·qt, nqt = n·qt, denom = max(|nqt|, 1)
__global__ __launch_bounds__(1024) void nred_kernel(
    const float* __restrict__ n_prev, float* __restrict__ out_n)
{
    const int t = threadIdx.x;
    const float ft = g_ft, it = g_it;
    float kqt = 0.f, nqt = 0.f;
    #pragma unroll
    for (int u = 0; u < MM / 1024; u++) {
        int i = t + u * 1024;
        float k = g_k[i];
        float q = g_qt[i];
        kqt += k * q;
        float n = ft * n_prev[i] + it * k;
        out_n[i] = n;
        nqt += n * q;
    }
    #pragma unroll
    for (int o = 16; o > 0; o >>= 1) {
        kqt += __shfl_down_sync(0xFFFFFFFFu, kqt, o);
        nqt += __shfl_down_sync(0xFFFFFFFFu, nqt, o);
    }
    __shared__ float sk[32], sn[32];
    if ((t & 31) == 0) { sk[t >> 5] = kqt; sn[t >> 5] = nqt; }
    __syncthreads();
    if (t < 32) {
        float a = sk[t], b = sn[t];
        #pragma unroll
        for (int o = 16; o > 0; o >>= 1) {
            a += __shfl_down_sync(0xFFFFFFFFu, a, o);
            b += __shfl_down_sync(0xFFFFFFFFu, b, o);
        }
        if (t == 0) {
            g_kqt = a;
            g_denom = fmaxf(fabsf(b), 1.0f);
        }
    }
}

// ---------------- kernel 3: cp stream -> C write + cp@qt + ht ----------------
// 4096 blocks (one per row), 512 threads. Fuses:
//   C[i][j] = ft*cp[i][j] + (it*v_i)*k[j]   (written to output)
//   s_i     = sum_j cp[i][j]*qt[j]
//   ht_i    = ot * (ft*s_i + it*v_i*kqt) / denom
__global__ __launch_bounds__(512) void cp_kernel(
    const float* __restrict__ cp, float* __restrict__ outC,
    float* __restrict__ outH)
{
    const int i = blockIdx.x;
    const int t = threadIdx.x;
    const float ft = g_ft;
    const float itv = g_it * g_v[i];

    const float4* cp4 = reinterpret_cast<const float4*>(cp + (size_t)i * MM);
    float4*       C4  = reinterpret_cast<float4*>(outC + (size_t)i * MM);
    const float4* k4  = reinterpret_cast<const float4*>(g_k);
    const float4* q4  = reinterpret_cast<const float4*>(g_qt);

    float s = 0.f;
    // 4096 floats = 1024 float4; 512 threads -> 2 float4 each, coalesced
    #pragma unroll
    for (int u = 0; u < 2; u++) {
        int j = t + u * 512;
        float4 c = cp4[j];
        float4 k = k4[j];
        float4 q = q4[j];
        float4 o;
        o.x = ft * c.x + itv * k.x;
        o.y = ft * c.y + itv * k.y;
        o.z = ft * c.z + itv * k.z;
        o.w = ft * c.w + itv * k.w;
        C4[j] = o;
        s += c.x * q.x + c.y * q.y + c.z * q.z + c.w * q.w;
    }

    #pragma unroll
    for (int o = 16; o > 0; o >>= 1) s += __shfl_down_sync(0xFFFFFFFFu, s, o);
    __shared__ float ws[16];
    if ((t & 31) == 0) ws[t >> 5] = s;
    __syncthreads();
    if (t < 16) {
        float v = ws[t];
        #pragma unroll
        for (int o = 8; o > 0; o >>= 1) v += __shfl_down_sync(0xFFFFu, v, o);
        if (t == 0) {
            outH[i] = g_ot * (ft * v + itv * g_kqt) / g_denom;
        }
    }
}

// ---------------- launch ----------------
extern "C" void kernel_launch(void* const* d_in, const int* in_sizes, int n_in,
                              void* d_out, int out_size)
{
    const float* x      = (const float*)d_in[0];
    const float* cp     = (const float*)d_in[1];
    const float* n_prev = (const float*)d_in[2];
    const float* Wq     = (const float*)d_in[3];
    const float* bq     = (const float*)d_in[4];
    const float* Wk     = (const float*)d_in[5];
    const float* bk     = (const float*)d_in[6];
    const float* Wv     = (const float*)d_in[7];
    const float* bV     = (const float*)d_in[8];
    const float* Wi     = (const float*)d_in[9];
    const float* bi     = (const float*)d_in[10];
    const float* Wf     = (const float*)d_in[11];
    const float* bf     = (const float*)d_in[12];
    const float* Wo     = (const float*)d_in[13];
    const float* bo     = (const float*)d_in[14];

    float* out  = (float*)d_out;
    float* outH = out;                       // ht: M
    float* outC = out + MM;                  // C : M*M
    float* outN = out + MM + (size_t)MM * MM; // n : M

    mv_kernel<<<3 * MM + 3, 256>>>(x, Wq, bq, Wk, bk, Wv, bV,
                                   Wi, bi, Wf, bf, Wo, bo);
    nred_kernel<<<1, 1024>>>(n_prev, outN);
    cp_kernel<<<MM, 512>>>(cp, outC, outH);
}

// round 2
// speedup vs baseline: 1.1341x; 1.1341x over previous
#include <cuda_runtime.h>
#include <math.h>

#define MM 4096
#define DD 2048
#define INV_SQRT_M 0.015625f   // 1/sqrt(4096) exact

// ---------------- device scratch ----------------
__device__ float g_qt[MM];
__device__ float g_k[MM];
__device__ float g_v[MM];
__device__ float g_it, g_ft, g_ot;
__device__ float g_kqt, g_denom;

// ---------------- kernel 1: fused q/k/v matvecs + gates ----------------
// grid = MM+1 blocks, 256 threads.
//   b <  MM : computes qt[b], k[b], v[b]  (3 rows, 6 LDG.128/thread front-batched)
//   b == MM : computes gates it, ft, ot from Wi, Wf, Wo
__global__ __launch_bounds__(256) void mv_kernel(
    const float* __restrict__ x,
    const float* __restrict__ Wq, const float* __restrict__ bq,
    const float* __restrict__ Wk, const float* __restrict__ bk,
    const float* __restrict__ Wv, const float* __restrict__ bV,
    const float* __restrict__ Wi, const float* __restrict__ bi,
    const float* __restrict__ Wf, const float* __restrict__ bf,
    const float* __restrict__ Wo, const float* __restrict__ bo)
{
    const int b = blockIdx.x;
    const int t = threadIdx.x;

    const float *rA, *rB, *rC;
    if (b < MM) {
        rA = Wq + (size_t)b * DD;
        rB = Wk + (size_t)b * DD;
        rC = Wv + (size_t)b * DD;
    } else {
        rA = Wi; rB = Wf; rC = Wo;
    }

    const float4* A4 = reinterpret_cast<const float4*>(rA);
    const float4* B4 = reinterpret_cast<const float4*>(rB);
    const float4* C4 = reinterpret_cast<const float4*>(rC);
    const float4* x4 = reinterpret_cast<const float4*>(x);

    // 6 independent streaming loads, front-batched (MLP=6)
    float4 a0 = __ldcs(&A4[t]);
    float4 a1 = __ldcs(&A4[t + 256]);
    float4 k0 = __ldcs(&B4[t]);
    float4 k1 = __ldcs(&B4[t + 256]);
    float4 v0 = __ldcs(&C4[t]);
    float4 v1 = __ldcs(&C4[t + 256]);
    float4 x0 = x4[t];
    float4 x1 = x4[t + 256];

    float sa = a0.x * x0.x + a0.y * x0.y + a0.z * x0.z + a0.w * x0.w
             + a1.x * x1.x + a1.y * x1.y + a1.z * x1.z + a1.w * x1.w;
    float sk = k0.x * x0.x + k0.y * x0.y + k0.z * x0.z + k0.w * x0.w
             + k1.x * x1.x + k1.y * x1.y + k1.z * x1.z + k1.w * x1.w;
    float sv = v0.x * x0.x + v0.y * x0.y + v0.z * x0.z + v0.w * x0.w
             + v1.x * x1.x + v1.y * x1.y + v1.z * x1.z + v1.w * x1.w;

    #pragma unroll
    for (int o = 16; o > 0; o >>= 1) {
        sa += __shfl_down_sync(0xFFFFFFFFu, sa, o);
        sk += __shfl_down_sync(0xFFFFFFFFu, sk, o);
        sv += __shfl_down_sync(0xFFFFFFFFu, sv, o);
    }

    __shared__ float wsa[8], wsk[8], wsv[8];
    if ((t & 31) == 0) {
        int w = t >> 5;
        wsa[w] = sa; wsk[w] = sk; wsv[w] = sv;
    }
    __syncthreads();
    if (t < 8) {
        float ra = wsa[t], rk = wsk[t], rv = wsv[t];
        #pragma unroll
        for (int o = 4; o > 0; o >>= 1) {
            ra += __shfl_down_sync(0xFFu, ra, o, 8);
            rk += __shfl_down_sync(0xFFu, rk, o, 8);
            rv += __shfl_down_sync(0xFFu, rv, o, 8);
        }
        if (t == 0) {
            if (b < MM) {
                g_qt[b] = ra + bq[b];
                g_k[b]  = INV_SQRT_M * (rk + bk[b]);
                g_v[b]  = rv + bV[b];
            } else {
                g_it = expf(ra + bi[0]);
                g_ft = expf(rk + bf[0]);
                float z = rv + bo[0];
                g_ot = 1.0f / (1.0f + expf(-z));
            }
        }
    }
}

// ---------------- kernel 2: n-update + tiny reductions ----------------
// n_i = ft*n_prev_i + it*k_i ; kqt = k·qt ; denom = max(|n·qt|, 1)
__global__ __launch_bounds__(1024) void nred_kernel(
    const float* __restrict__ n_prev, float* __restrict__ out_n)
{
    const int t = threadIdx.x;
    const float ft = g_ft, it = g_it;
    float kqt = 0.f, nqt = 0.f;
    #pragma unroll
    for (int u = 0; u < MM / 1024; u++) {
        int i = t + u * 1024;
        float k = g_k[i];
        float q = g_qt[i];
        kqt += k * q;
        float n = ft * n_prev[i] + it * k;
        out_n[i] = n;
        nqt += n * q;
    }
    #pragma unroll
    for (int o = 16; o > 0; o >>= 1) {
        kqt += __shfl_down_sync(0xFFFFFFFFu, kqt, o);
        nqt += __shfl_down_sync(0xFFFFFFFFu, nqt, o);
    }
    __shared__ float sk[32], sn[32];
    if ((t & 31) == 0) { sk[t >> 5] = kqt; sn[t >> 5] = nqt; }
    __syncthreads();
    if (t < 32) {
        float a = sk[t], b = sn[t];
        #pragma unroll
        for (int o = 16; o > 0; o >>= 1) {
            a += __shfl_down_sync(0xFFFFFFFFu, a, o);
            b += __shfl_down_sync(0xFFFFFFFFu, b, o);
        }
        if (t == 0) {
            g_kqt = a;
            g_denom = fmaxf(fabsf(b), 1.0f);
        }
    }
}

// ---------------- kernel 3: cp stream -> C write + cp@qt + ht ----------------
// 2 rows per block, 512 threads: 4 front-batched streaming loads per thread.
//   C[i][j] = ft*cp[i][j] + (it*v_i)*k[j]
//   s_i     = sum_j cp[i][j]*qt[j]
//   ht_i    = ot*(ft*s_i + it*v_i*kqt)/denom
__global__ __launch_bounds__(512) void cp_kernel(
    const float* __restrict__ cp, float* __restrict__ outC,
    float* __restrict__ outH)
{
    const int i0 = blockIdx.x * 2;
    const int i1 = i0 + 1;
    const int t  = threadIdx.x;
    const float ft   = g_ft;
    const float it   = g_it;
    const float itv0 = it * g_v[i0];
    const float itv1 = it * g_v[i1];

    const float4* cpA = reinterpret_cast<const float4*>(cp   + (size_t)i0 * MM);
    const float4* cpB = reinterpret_cast<const float4*>(cp   + (size_t)i1 * MM);
    float4*       CA  = reinterpret_cast<float4*>(outC + (size_t)i0 * MM);
    float4*       CB  = reinterpret_cast<float4*>(outC + (size_t)i1 * MM);
    const float4* k4  = reinterpret_cast<const float4*>(g_k);
    const float4* q4  = reinterpret_cast<const float4*>(g_qt);

    const int j0 = t;
    const int j1 = t + 512;

    // 4 independent streaming loads front-batched (MLP=4)
    float4 c00 = __ldcs(&cpA[j0]);
    float4 c01 = __ldcs(&cpA[j1]);
    float4 c10 = __ldcs(&cpB[j0]);
    float4 c11 = __ldcs(&cpB[j1]);
    float4 ka = k4[j0], kb = k4[j1];
    float4 qa = q4[j0], qb = q4[j1];

    float4 o;
    o.x = ft * c00.x + itv0 * ka.x; o.y = ft * c00.y + itv0 * ka.y;
    o.z = ft * c00.z + itv0 * ka.z; o.w = ft * c00.w + itv0 * ka.w;
    __stcs(&CA[j0], o);
    o.x = ft * c01.x + itv0 * kb.x; o.y = ft * c01.y + itv0 * kb.y;
    o.z = ft * c01.z + itv0 * kb.z; o.w = ft * c01.w + itv0 * kb.w;
    __stcs(&CA[j1], o);
    o.x = ft * c10.x + itv1 * ka.x; o.y = ft * c10.y + itv1 * ka.y;
    o.z = ft * c10.z + itv1 * ka.z; o.w = ft * c10.w + itv1 * ka.w;
    __stcs(&CB[j0], o);
    o.x = ft * c11.x + itv1 * kb.x; o.y = ft * c11.y + itv1 * kb.y;
    o.z = ft * c11.z + itv1 * kb.z; o.w = ft * c11.w + itv1 * kb.w;
    __stcs(&CB[j1], o);

    float s0 = c00.x * qa.x + c00.y * qa.y + c00.z * qa.z + c00.w * qa.w
             + c01.x * qb.x + c01.y * qb.y + c01.z * qb.z + c01.w * qb.w;
    float s1 = c10.x * qa.x + c10.y * qa.y + c10.z * qa.z + c10.w * qa.w
             + c11.x * qb.x + c11.y * qb.y + c11.z * qb.z + c11.w * qb.w;

    #pragma unroll
    for (int o2 = 16; o2 > 0; o2 >>= 1) {
        s0 += __shfl_down_sync(0xFFFFFFFFu, s0, o2);
        s1 += __shfl_down_sync(0xFFFFFFFFu, s1, o2);
    }
    __shared__ float ws0[16], ws1[16];
    if ((t & 31) == 0) { ws0[t >> 5] = s0; ws1[t >> 5] = s1; }
    __syncthreads();
    if (t < 16) {
        float a = ws0[t], b = ws1[t];
        #pragma unroll
        for (int o2 = 8; o2 > 0; o2 >>= 1) {
            a += __shfl_down_sync(0xFFFFu, a, o2, 16);
            b += __shfl_down_sync(0xFFFFu, b, o2, 16);
        }
        if (t == 0) {
            const float inv = g_ot / g_denom;
            const float kqt = g_kqt;
            outH[i0] = inv * (ft * a + itv0 * kqt);
            outH[i1] = inv * (ft * b + itv1 * kqt);
        }
    }
}

// ---------------- launch ----------------
extern "C" void kernel_launch(void* const* d_in, const int* in_sizes, int n_in,
                              void* d_out, int out_size)
{
    const float* x      = (const float*)d_in[0];
    const float* cp     = (const float*)d_in[1];
    const float* n_prev = (const float*)d_in[2];
    const float* Wq     = (const float*)d_in[3];
    const float* bq     = (const float*)d_in[4];
    const float* Wk     = (const float*)d_in[5];
    const float* bk     = (const float*)d_in[6];
    const float* Wv     = (const float*)d_in[7];
    const float* bV     = (const float*)d_in[8];
    const float* Wi     = (const float*)d_in[9];
    const float* bi     = (const float*)d_in[10];
    const float* Wf     = (const float*)d_in[11];
    const float* bf     = (const float*)d_in[12];
    const float* Wo     = (const float*)d_in[13];
    const float* bo     = (const float*)d_in[14];

    float* out  = (float*)d_out;
    float* outH = out;                        // ht: M
    float* outC = out + MM;                   // C : M*M
    float* outN = out + MM + (size_t)MM * MM; // n : M

    mv_kernel<<<MM + 1, 256>>>(x, Wq, bq, Wk, bk, Wv, bV,
                               Wi, bi, Wf, bf, Wo, bo);
    nred_kernel<<<1, 1024>>>(n_prev, outN);
    cp_kernel<<<MM / 2, 512>>>(cp, outC, outH);
}